// round 2
// baseline (speedup 1.0000x reference)
#include <cuda_runtime.h>
#include <cuda_fp16.h>
#include <cstdint>

#define BATCH 1048576
#define HID 64

// ---------------- device-global scratch (no allocations allowed) ----------------
// t_j = tanh(pre-BN activations) for layers 0..4, fp16: 5 * 128 MB
__device__ __half g_t[(size_t)5 * BATCH * HID];
__device__ float  g_sums[6][2][64];   // [stat-slot][sum/sqsum][feature]
__device__ float  g_aff [6][2][64];   // [stat-slot][scale/shift][feature]

// ---------------- helpers ----------------
__device__ __forceinline__ float my_tanh(float x) {
    // tanh(x) = 1 - 2/(e^{2x}+1); 2 MUFU, ~1e-6 rel err, saturates correctly
    float e = __expf(2.0f * x);
    return 1.0f - __fdividef(2.0f, e + 1.0f);
}

__device__ __forceinline__ uint32_t tf32u(float f) {
    uint32_t u;
    asm("cvt.rna.tf32.f32 %0, %1;" : "=r"(u) : "f"(f));
    return u;
}

__device__ __forceinline__ void mma_tf32(float c[4],
                                         uint32_t a0, uint32_t a1, uint32_t a2, uint32_t a3,
                                         uint32_t b0, uint32_t b1) {
    asm volatile(
        "mma.sync.aligned.m16n8k8.row.col.f32.tf32.tf32.f32 "
        "{%0,%1,%2,%3}, {%4,%5,%6,%7}, {%8,%9}, {%0,%1,%2,%3};\n"
        : "+f"(c[0]), "+f"(c[1]), "+f"(c[2]), "+f"(c[3])
        : "r"(a0), "r"(a1), "r"(a2), "r"(a3), "r"(b0), "r"(b1));
}

// ---------------- kernels ----------------

__global__ void zero_kernel() {
    int t = threadIdx.x + blockIdx.x * blockDim.x;
    if (t < 6 * 2 * 64) ((float*)g_sums)[t] = 0.0f;
}

// batch stats of x [1M,4] -> g_sums[0]
__global__ __launch_bounds__(256) void xstats_kernel(const float* __restrict__ x) {
    __shared__ float sm[8];
    int tid = threadIdx.x;
    if (tid < 8) sm[tid] = 0.0f;
    __syncthreads();
    float s[4] = {0.f, 0.f, 0.f, 0.f}, q[4] = {0.f, 0.f, 0.f, 0.f};
    const float4* x4 = (const float4*)x;
    size_t base = (size_t)blockIdx.x * 256 + tid;
    #pragma unroll
    for (int i = 0; i < 4; i++) {
        float4 v = x4[base + (size_t)i * 262144];
        s[0] += v.x; q[0] += v.x * v.x;
        s[1] += v.y; q[1] += v.y * v.y;
        s[2] += v.z; q[2] += v.z * v.z;
        s[3] += v.w; q[3] += v.w * v.w;
    }
    #pragma unroll
    for (int k = 0; k < 4; k++)
        for (int off = 16; off; off >>= 1) {
            s[k] += __shfl_xor_sync(0xffffffffu, s[k], off);
            q[k] += __shfl_xor_sync(0xffffffffu, q[k], off);
        }
    if ((tid & 31) == 0) {
        #pragma unroll
        for (int k = 0; k < 4; k++) {
            atomicAdd(&sm[k], s[k]);
            atomicAdd(&sm[4 + k], q[k]);
        }
    }
    __syncthreads();
    if (tid < 8) atomicAdd(&g_sums[0][tid >> 2][tid & 3], sm[tid]);
}

// sums -> (scale, shift)
__global__ void fin_kernel(int idx, const float* __restrict__ gamma,
                           const float* __restrict__ beta, int count) {
    int t = threadIdx.x;
    if (t >= count) return;
    const float invN = 1.0f / 1048576.0f;
    float mu  = g_sums[idx][0][t] * invN;
    float var = g_sums[idx][1][t] * invN - mu * mu;
    float sc = gamma[t] * rsqrtf(var + 1e-5f);
    g_aff[idx][0][t] = sc;
    g_aff[idx][1][t] = beta[t] - mu * sc;
}

// first layer: t0 = tanh(bn0(x) @ W0 + b0); stats(t0) -> g_sums[1]
// 256 threads, 8 threads/row (each thread: 8 output cols), 1024 rows/CTA
__global__ __launch_bounds__(256) void k1_kernel(const float* __restrict__ x,
                                                 const float* __restrict__ W0,
                                                 const float* __restrict__ b0) {
    __shared__ float Ws[4][64];
    __shared__ float s_sum[64], s_sq[64];
    __shared__ float affs[4], affb[4];
    int tid = threadIdx.x;
    if (tid < 256) Ws[tid >> 6][tid & 63] = W0[tid];
    if (tid < 64) { s_sum[tid] = 0.f; s_sq[tid] = 0.f; }
    if (tid < 4) { affs[tid] = g_aff[0][0][tid]; affb[tid] = g_aff[0][1][tid]; }
    __syncthreads();

    int g = tid & 7, sub = tid >> 3;
    int cb = g * 8;
    float w0r[8], w1r[8], w2r[8], w3r[8], bb[8];
    #pragma unroll
    for (int e = 0; e < 8; e++) {
        w0r[e] = Ws[0][cb + e]; w1r[e] = Ws[1][cb + e];
        w2r[e] = Ws[2][cb + e]; w3r[e] = Ws[3][cb + e];
        bb[e] = b0[cb + e];
    }
    float a0s = affs[0], a1s = affs[1], a2s = affs[2], a3s = affs[3];
    float a0b = affb[0], a1b = affb[1], a2b = affb[2], a3b = affb[3];
    float s[8], q[8];
    #pragma unroll
    for (int e = 0; e < 8; e++) { s[e] = 0.f; q[e] = 0.f; }

    size_t row0 = (size_t)blockIdx.x * 1024;
    const float4* x4 = (const float4*)x;
    uint4* outp = (uint4*)g_t;  // layer 0

    for (int it = 0; it < 32; it++) {
        size_t r = row0 + it * 32 + sub;
        float4 xv = x4[r];
        float h0 = xv.x * a0s + a0b;
        float h1 = xv.y * a1s + a1b;
        float h2 = xv.z * a2s + a2b;
        float h3 = xv.w * a3s + a3b;
        union { uint4 u; __half h[8]; } pk;
        #pragma unroll
        for (int e = 0; e < 8; e++) {
            float z = bb[e] + h0 * w0r[e] + h1 * w1r[e] + h2 * w2r[e] + h3 * w3r[e];
            float v = my_tanh(z);
            s[e] += v; q[e] += v * v;
            pk.h[e] = __float2half_rn(v);
        }
        outp[r * 8 + g] = pk.u;
    }

    // reduce over the 4 sub-rows sharing this g within the warp (lane bits 3,4)
    #pragma unroll
    for (int e = 0; e < 8; e++) {
        s[e] += __shfl_xor_sync(0xffffffffu, s[e], 8);
        q[e] += __shfl_xor_sync(0xffffffffu, q[e], 8);
        s[e] += __shfl_xor_sync(0xffffffffu, s[e], 16);
        q[e] += __shfl_xor_sync(0xffffffffu, q[e], 16);
    }
    if ((tid & 24) == 0) {  // lane 0..7 of each warp
        #pragma unroll
        for (int e = 0; e < 8; e++) {
            atomicAdd(&s_sum[cb + e], s[e]);
            atomicAdd(&s_sq[cb + e], q[e]);
        }
    }
    __syncthreads();
    if (tid < 64) {
        atomicAdd(&g_sums[1][0][tid], s_sum[tid]);
        atomicAdd(&g_sums[1][1][tid], s_sq[tid]);
    }
}

// mid layer m (1..4): build y_m = sum_{j<m} aff[1+j](t_j) on the fly,
// t_m = tanh(y_m @ W_hid[m-1] + b), stats -> g_sums[m+1].
// 128 threads (4 warps), 4 chunks x 64 rows = 256 rows/CTA, grid 4096.
__global__ __launch_bounds__(128) void mid_kernel(int m,
                                                  const float* __restrict__ W,
                                                  const float* __restrict__ b) {
    __shared__ float As[64][68];   // conflict-free A fragment loads
    __shared__ float Ws[64][72];   // conflict-free B fragment loads
    __shared__ float Bs[64];
    __shared__ float Saff[4][2][64];
    __shared__ float s_sum[64], s_sq[64];

    int tid = threadIdx.x;
    int warp = tid >> 5, lane = tid & 31;

    for (int i = tid; i < 64 * 64; i += 128)
        Ws[i >> 6][i & 63] = W[i];
    if (tid < 64) { Bs[tid] = b[tid]; s_sum[tid] = 0.f; s_sq[tid] = 0.f; }
    for (int i = tid; i < m * 128; i += 128) {
        int j = i >> 7, rest = i & 127;
        Saff[j][rest >> 6][rest & 63] = g_aff[1 + j][rest >> 6][rest & 63];
    }
    __syncthreads();

    size_t row0 = (size_t)blockIdx.x * 256;
    int cb = (tid & 7) * 8;
    const int r_base = warp * 16;
    __half2* toutp = (__half2*)(g_t + (size_t)m * BATCH * HID);

    float ssum[16], ssq[16];
    #pragma unroll
    for (int i = 0; i < 16; i++) { ssum[i] = 0.f; ssq[i] = 0.f; }

    for (int chunk = 0; chunk < 4; chunk++) {
        size_t R = row0 + chunk * 64;

        // ---- build As = y_m (fp32) for rows R..R+63 ----
        {
            float acc[4][8];
            #pragma unroll
            for (int i = 0; i < 4; i++)
                #pragma unroll
                for (int e = 0; e < 8; e++) acc[i][e] = 0.f;
            for (int j = 0; j < m; j++) {
                const uint4* tv = (const uint4*)(g_t + (size_t)j * BATCH * HID + R * HID);
                float sc[8], sh[8];
                #pragma unroll
                for (int e = 0; e < 8; e++) {
                    sc[e] = Saff[j][0][cb + e];
                    sh[e] = Saff[j][1][cb + e];
                }
                #pragma unroll
                for (int i = 0; i < 4; i++) {
                    union { uint4 u; __half2 h2[4]; } cv;
                    cv.u = tv[tid + i * 128];
                    #pragma unroll
                    for (int p = 0; p < 4; p++) {
                        float2 f = __half22float2(cv.h2[p]);
                        acc[i][2 * p]     += sc[2 * p] * f.x + sh[2 * p];
                        acc[i][2 * p + 1] += sc[2 * p + 1] * f.y + sh[2 * p + 1];
                    }
                }
            }
            #pragma unroll
            for (int i = 0; i < 4; i++) {
                int r = (tid + i * 128) >> 3;
                #pragma unroll
                for (int e = 0; e < 8; e++) As[r][cb + e] = acc[i][e];
            }
        }
        __syncthreads();

        // ---- MMA: warp computes rows r_base..r_base+15 x 64 cols, K=64 ----
        float c[8][4];
        #pragma unroll
        for (int n8 = 0; n8 < 8; n8++)
            #pragma unroll
            for (int k = 0; k < 4; k++) c[n8][k] = 0.f;

        #pragma unroll
        for (int k8 = 0; k8 < 8; k8++) {
            int k0 = k8 * 8;
            int ar = r_base + (lane >> 2);
            int ac = k0 + (lane & 3);
            float fa0 = As[ar][ac],     fa1 = As[ar + 8][ac];
            float fa2 = As[ar][ac + 4], fa3 = As[ar + 8][ac + 4];
            uint32_t ah0 = tf32u(fa0), ah1 = tf32u(fa1);
            uint32_t ah2 = tf32u(fa2), ah3 = tf32u(fa3);
            uint32_t al0 = tf32u(fa0 - __uint_as_float(ah0));
            uint32_t al1 = tf32u(fa1 - __uint_as_float(ah1));
            uint32_t al2 = tf32u(fa2 - __uint_as_float(ah2));
            uint32_t al3 = tf32u(fa3 - __uint_as_float(ah3));
            #pragma unroll
            for (int n8 = 0; n8 < 8; n8++) {
                int n0 = n8 * 8;
                uint32_t bf0 = tf32u(Ws[k0 + (lane & 3)][n0 + (lane >> 2)]);
                uint32_t bf1 = tf32u(Ws[k0 + (lane & 3) + 4][n0 + (lane >> 2)]);
                mma_tf32(c[n8], ah0, ah1, ah2, ah3, bf0, bf1);  // hi term
                mma_tf32(c[n8], al0, al1, al2, al3, bf0, bf1);  // A-lo correction
            }
        }

        // ---- epilogue: bias + tanh + fp16 store + stats ----
        size_t grow = R + r_base + (lane >> 2);
        #pragma unroll
        for (int n8 = 0; n8 < 8; n8++) {
            int col = n8 * 8 + (lane & 3) * 2;
            float bb0 = Bs[col], bb1 = Bs[col + 1];
            float v00 = my_tanh(c[n8][0] + bb0);
            float v01 = my_tanh(c[n8][1] + bb1);
            float v10 = my_tanh(c[n8][2] + bb0);
            float v11 = my_tanh(c[n8][3] + bb1);
            toutp[grow * 32 + (col >> 1)]       = __floats2half2_rn(v00, v01);
            toutp[(grow + 8) * 32 + (col >> 1)] = __floats2half2_rn(v10, v11);
            ssum[2 * n8]     += v00 + v10;
            ssum[2 * n8 + 1] += v01 + v11;
            ssq[2 * n8]      += v00 * v00 + v10 * v10;
            ssq[2 * n8 + 1]  += v01 * v01 + v11 * v11;
        }
        __syncthreads();
    }

    // reduce stats over lanes sharing (lane&3)
    #pragma unroll
    for (int i = 0; i < 16; i++) {
        ssum[i] += __shfl_xor_sync(0xffffffffu, ssum[i], 4);
        ssq[i]  += __shfl_xor_sync(0xffffffffu, ssq[i], 4);
        ssum[i] += __shfl_xor_sync(0xffffffffu, ssum[i], 8);
        ssq[i]  += __shfl_xor_sync(0xffffffffu, ssq[i], 8);
        ssum[i] += __shfl_xor_sync(0xffffffffu, ssum[i], 16);
        ssq[i]  += __shfl_xor_sync(0xffffffffu, ssq[i], 16);
    }
    if (lane < 4) {
        #pragma unroll
        for (int n8 = 0; n8 < 8; n8++) {
            int col = n8 * 8 + lane * 2;
            atomicAdd(&s_sum[col],     ssum[2 * n8]);
            atomicAdd(&s_sum[col + 1], ssum[2 * n8 + 1]);
            atomicAdd(&s_sq[col],      ssq[2 * n8]);
            atomicAdd(&s_sq[col + 1],  ssq[2 * n8 + 1]);
        }
    }
    __syncthreads();
    if (tid < 64) {
        atomicAdd(&g_sums[m + 1][0][tid], s_sum[tid]);
        atomicAdd(&g_sums[m + 1][1][tid], s_sq[tid]);
    }
}

// output: y5 = sum_{j=0..4} aff[1+j](t_j);  out = y5 @ Wout + bout
// 256 threads, 8 threads/row, 1024 rows/CTA
__global__ __launch_bounds__(256) void out_kernel(const float* __restrict__ Wout,
                                                  const float* __restrict__ bout,
                                                  float* __restrict__ out) {
    __shared__ float Ws[64][4];
    __shared__ float Saff[5][2][64];
    __shared__ float bb[3];
    int tid = threadIdx.x;
    if (tid < 192) Ws[tid / 3][tid % 3] = Wout[tid];
    if (tid < 3) bb[tid] = bout[tid];
    for (int i = tid; i < 5 * 128; i += 256) {
        int j = i >> 7, rest = i & 127;
        Saff[j][rest >> 6][rest & 63] = g_aff[1 + j][rest >> 6][rest & 63];
    }
    __syncthreads();

    int g = tid & 7, sub = tid >> 3;
    int cb = g * 8;
    float w[8][3];
    #pragma unroll
    for (int e = 0; e < 8; e++) {
        w[e][0] = Ws[cb + e][0];
        w[e][1] = Ws[cb + e][1];
        w[e][2] = Ws[cb + e][2];
    }

    size_t row0 = (size_t)blockIdx.x * 1024;
    for (int it = 0; it < 32; it++) {
        size_t r = row0 + it * 32 + sub;
        float y[8];
        #pragma unroll
        for (int e = 0; e < 8; e++) y[e] = 0.f;
        #pragma unroll
        for (int j = 0; j < 5; j++) {
            union { uint4 u; __half2 h2[4]; } cv;
            cv.u = ((const uint4*)(g_t + (size_t)j * BATCH * HID))[r * 8 + g];
            #pragma unroll
            for (int p = 0; p < 4; p++) {
                float2 f = __half22float2(cv.h2[p]);
                y[2 * p]     += Saff[j][0][cb + 2 * p] * f.x + Saff[j][1][cb + 2 * p];
                y[2 * p + 1] += Saff[j][0][cb + 2 * p + 1] * f.y + Saff[j][1][cb + 2 * p + 1];
            }
        }
        float p0 = 0.f, p1 = 0.f, p2 = 0.f;
        #pragma unroll
        for (int e = 0; e < 8; e++) {
            p0 += y[e] * w[e][0];
            p1 += y[e] * w[e][1];
            p2 += y[e] * w[e][2];
        }
        #pragma unroll
        for (int off = 1; off < 8; off <<= 1) {
            p0 += __shfl_xor_sync(0xffffffffu, p0, off);
            p1 += __shfl_xor_sync(0xffffffffu, p1, off);
            p2 += __shfl_xor_sync(0xffffffffu, p2, off);
        }
        if (g == 0) {
            out[r * 3 + 0] = p0 + bb[0];
            out[r * 3 + 1] = p1 + bb[1];
            out[r * 3 + 2] = p2 + bb[2];
        }
    }
}

// ---------------- launch ----------------
extern "C" void kernel_launch(void* const* d_in, const int* in_sizes, int n_in,
                              void* d_out, int out_size) {
    const float* x    = (const float*)d_in[0];
    const float* bn0g = (const float*)d_in[1];
    const float* bn0b = (const float*)d_in[2];
    const float* W0   = (const float*)d_in[3];
    const float* b0   = (const float*)d_in[4];
    const float* g0   = (const float*)d_in[5];
    const float* be0  = (const float*)d_in[6];
    const float* Wh   = (const float*)d_in[7];
    const float* bh   = (const float*)d_in[8];
    const float* gh   = (const float*)d_in[9];
    const float* beh  = (const float*)d_in[10];
    const float* Wo   = (const float*)d_in[11];
    const float* bo   = (const float*)d_in[12];
    float* out = (float*)d_out;

    zero_kernel<<<3, 256>>>();
    xstats_kernel<<<1024, 256>>>(x);
    fin_kernel<<<1, 64>>>(0, bn0g, bn0b, 4);
    k1_kernel<<<1024, 256>>>(x, W0, b0);
    fin_kernel<<<1, 64>>>(1, g0, be0, 64);
    for (int m = 1; m <= 4; m++) {
        mid_kernel<<<4096, 128>>>(m, Wh + (size_t)(m - 1) * 4096, bh + (m - 1) * 64);
        fin_kernel<<<1, 64>>>(m + 1, gh + (m - 1) * 64, beh + (m - 1) * 64, 64);
    }
    out_kernel<<<1024, 256>>>(Wo, bo, out);
}

// round 5
// speedup vs baseline: 1.0094x; 1.0094x over previous
#include <cuda_runtime.h>
#include <cuda_fp16.h>
#include <cstdint>

#define BATCH 1048576
#define HID 64

// ---------------- device-global scratch (no allocations allowed) ----------------
__device__ __half g_t[(size_t)5 * BATCH * HID];   // t_j = tanh(pre-BN act), fp16
__device__ float  g_sums[6][2][64];               // [slot][sum/sqsum][feature]
__device__ float  g_aff [6][2][64];               // [slot][scale/shift][feature]
__device__ uint4  g_Bfrag[4 * 4 * 8 * 32];        // pre-packed B fragments [j][k4][n8][lane]
__device__ float  g_cbias[64];                    // combined bias for current layer

// ---------------- helpers ----------------
__device__ __forceinline__ float my_tanh(float x) {
    float e = __expf(2.0f * x);
    return 1.0f - __fdividef(2.0f, e + 1.0f);
}

__device__ __forceinline__ void mma_f16(float c[4],
                                        uint32_t a0, uint32_t a1, uint32_t a2, uint32_t a3,
                                        uint32_t b0, uint32_t b1) {
    asm volatile(
        "mma.sync.aligned.m16n8k16.row.col.f32.f16.f16.f32 "
        "{%0,%1,%2,%3}, {%4,%5,%6,%7}, {%8,%9}, {%0,%1,%2,%3};\n"
        : "+f"(c[0]), "+f"(c[1]), "+f"(c[2]), "+f"(c[3])
        : "r"(a0), "r"(a1), "r"(a2), "r"(a3), "r"(b0), "r"(b1));
}

__device__ __forceinline__ uint32_t pack_h2(float a, float b) {
    __half2 h = __floats2half2_rn(a, b);
    return *(uint32_t*)&h;
}

// ---------------- small kernels ----------------

__global__ void zero_kernel() {
    int t = threadIdx.x + blockIdx.x * blockDim.x;
    if (t < 6 * 2 * 64) ((float*)g_sums)[t] = 0.0f;
}

__global__ __launch_bounds__(256) void xstats_kernel(const float* __restrict__ x) {
    __shared__ float sm[8];
    int tid = threadIdx.x;
    if (tid < 8) sm[tid] = 0.0f;
    __syncthreads();
    float s[4] = {0.f, 0.f, 0.f, 0.f}, q[4] = {0.f, 0.f, 0.f, 0.f};
    const float4* x4 = (const float4*)x;
    size_t base = (size_t)blockIdx.x * 256 + tid;
    #pragma unroll
    for (int i = 0; i < 4; i++) {
        float4 v = x4[base + (size_t)i * 262144];
        s[0] += v.x; q[0] += v.x * v.x;
        s[1] += v.y; q[1] += v.y * v.y;
        s[2] += v.z; q[2] += v.z * v.z;
        s[3] += v.w; q[3] += v.w * v.w;
    }
    #pragma unroll
    for (int k = 0; k < 4; k++)
        for (int off = 16; off; off >>= 1) {
            s[k] += __shfl_xor_sync(0xffffffffu, s[k], off);
            q[k] += __shfl_xor_sync(0xffffffffu, q[k], off);
        }
    if ((tid & 31) == 0) {
        #pragma unroll
        for (int k = 0; k < 4; k++) {
            atomicAdd(&sm[k], s[k]);
            atomicAdd(&sm[4 + k], q[k]);
        }
    }
    __syncthreads();
    if (tid < 8) atomicAdd(&g_sums[0][tid >> 2][tid & 3], sm[tid]);
}

__global__ void fin_kernel(int idx, const float* __restrict__ gamma,
                           const float* __restrict__ beta, int count) {
    int t = threadIdx.x;
    if (t >= count) return;
    const float invN = 1.0f / 1048576.0f;
    float mu  = g_sums[idx][0][t] * invN;
    float var = g_sums[idx][1][t] * invN - mu * mu;
    float sc = gamma[t] * rsqrtf(var + 1e-5f);
    g_aff[idx][0][t] = sc;
    g_aff[idx][1][t] = beta[t] - mu * sc;
}

// pre-pack Weff_{j} = diag(sc_{j+1}) @ W into mma B-fragment layout (hi/lo fp16),
// plus combined bias c[n] = b[n] + sum_j sum_k sh_{j+1}[k] W[k][n]
__global__ void prep_kernel(int m, const float* __restrict__ W, const float* __restrict__ b) {
    int blk = blockIdx.x;
    if (blk == m * 4) {
        int n = threadIdx.x;
        if (n < 64) {
            float acc = b[n];
            for (int j = 0; j < m; j++)
                for (int k = 0; k < 64; k++)
                    acc += g_aff[1 + j][1][k] * W[k * 64 + n];
            g_cbias[n] = acc;
        }
        return;
    }
    int j = blk >> 2, k4 = blk & 3;
    int t = threadIdx.x;
    int n8 = t >> 5, lane = t & 31, gid = lane >> 2, tig = lane & 3;
    int n = n8 * 8 + gid;
    int kb = k4 * 16 + 2 * tig;
    float w0 = g_aff[1 + j][0][kb]     * W[kb * 64 + n];
    float w1 = g_aff[1 + j][0][kb + 1] * W[(kb + 1) * 64 + n];
    float w8 = g_aff[1 + j][0][kb + 8] * W[(kb + 8) * 64 + n];
    float w9 = g_aff[1 + j][0][kb + 9] * W[(kb + 9) * 64 + n];
    __half h0 = __float2half_rn(w0), h1 = __float2half_rn(w1);
    __half h8 = __float2half_rn(w8), h9 = __float2half_rn(w9);
    uint4 v;
    {
        __half2 p0 = __halves2half2(h0, h1); v.x = *(uint32_t*)&p0;
        __half2 p1 = __halves2half2(h8, h9); v.y = *(uint32_t*)&p1;
    }
    v.z = pack_h2(w0 - __half2float(h0), w1 - __half2float(h1));
    v.w = pack_h2(w8 - __half2float(h8), w9 - __half2float(h9));
    g_Bfrag[((j * 4 + k4) * 8 + n8) * 32 + lane] = v;
}

// first layer: t0 = tanh(bn0(x) @ W0 + b0); stats(t0) -> g_sums[1]
__global__ __launch_bounds__(256) void k1_kernel(const float* __restrict__ x,
                                                 const float* __restrict__ W0,
                                                 const float* __restrict__ b0) {
    __shared__ float Ws[4][64];
    __shared__ float s_sum[64], s_sq[64];
    __shared__ float affs[4], affb[4];
    int tid = threadIdx.x;
    if (tid < 256) Ws[tid >> 6][tid & 63] = W0[tid];
    if (tid < 64) { s_sum[tid] = 0.f; s_sq[tid] = 0.f; }
    if (tid < 4) { affs[tid] = g_aff[0][0][tid]; affb[tid] = g_aff[0][1][tid]; }
    __syncthreads();

    int g = tid & 7, sub = tid >> 3;
    int cb = g * 8;
    float w0r[8], w1r[8], w2r[8], w3r[8], bb[8];
    #pragma unroll
    for (int e = 0; e < 8; e++) {
        w0r[e] = Ws[0][cb + e]; w1r[e] = Ws[1][cb + e];
        w2r[e] = Ws[2][cb + e]; w3r[e] = Ws[3][cb + e];
        bb[e] = b0[cb + e];
    }
    float a0s = affs[0], a1s = affs[1], a2s = affs[2], a3s = affs[3];
    float a0b = affb[0], a1b = affb[1], a2b = affb[2], a3b = affb[3];
    float s[8], q[8];
    #pragma unroll
    for (int e = 0; e < 8; e++) { s[e] = 0.f; q[e] = 0.f; }

    size_t row0 = (size_t)blockIdx.x * 256;
    const float4* x4 = (const float4*)x;
    uint4* outp = (uint4*)g_t;

    #pragma unroll
    for (int it = 0; it < 8; it++) {
        size_t r = row0 + it * 32 + sub;
        float4 xv = x4[r];
        float h0 = xv.x * a0s + a0b;
        float h1 = xv.y * a1s + a1b;
        float h2 = xv.z * a2s + a2b;
        float h3 = xv.w * a3s + a3b;
        union { uint4 u; __half h[8]; } pk;
        #pragma unroll
        for (int e = 0; e < 8; e++) {
            float z = bb[e] + h0 * w0r[e] + h1 * w1r[e] + h2 * w2r[e] + h3 * w3r[e];
            float v = my_tanh(z);
            s[e] += v; q[e] += v * v;
            pk.h[e] = __float2half_rn(v);
        }
        outp[r * 8 + g] = pk.u;
    }

    #pragma unroll
    for (int e = 0; e < 8; e++) {
        s[e] += __shfl_xor_sync(0xffffffffu, s[e], 8);
        q[e] += __shfl_xor_sync(0xffffffffu, q[e], 8);
        s[e] += __shfl_xor_sync(0xffffffffu, s[e], 16);
        q[e] += __shfl_xor_sync(0xffffffffu, q[e], 16);
    }
    if ((tid & 24) == 0) {
        #pragma unroll
        for (int e = 0; e < 8; e++) {
            atomicAdd(&s_sum[cb + e], s[e]);
            atomicAdd(&s_sq[cb + e], q[e]);
        }
    }
    __syncthreads();
    if (tid < 64) {
        atomicAdd(&g_sums[1][0][tid], s_sum[tid]);
        atomicAdd(&g_sums[1][1][tid], s_sq[tid]);
    }
}

// mid layer m: z = sum_{j<m} t_j @ Weff_j + c; t_m = tanh(z); stats -> g_sums[m+1]
// 256 threads (8 warps), 256 rows/CTA (2 sub-chunks of 128), grid 4096.
// A fragments straight from gmem fp16; B fragments pre-packed (hi+lo) from L1/L2.
template <int M>
__global__ void __launch_bounds__(256) midk(int mslot) {
    __shared__ float s_sum[64], s_sq[64];
    int tid = threadIdx.x, warp = tid >> 5, lane = tid & 31;
    int gid = lane >> 2, tig = lane & 3;
    if (tid < 64) { s_sum[tid] = 0.f; s_sq[tid] = 0.f; }
    __syncthreads();

    float C[2][8][4];
    #pragma unroll
    for (int s = 0; s < 2; s++)
        #pragma unroll
        for (int n8 = 0; n8 < 8; n8++)
            #pragma unroll
            for (int e = 0; e < 4; e++) C[s][n8][e] = 0.f;

    size_t R0 = (size_t)blockIdx.x * 256;

    #pragma unroll
    for (int j = 0; j < M; j++) {
        const uint32_t* tp = (const uint32_t*)(g_t + (size_t)j * BATCH * HID);
        #pragma unroll
        for (int k4 = 0; k4 < 4; k4++) {
            uint4 bf[8];
            #pragma unroll
            for (int n8 = 0; n8 < 8; n8++)
                bf[n8] = g_Bfrag[((j * 4 + k4) * 8 + n8) * 32 + lane];
            #pragma unroll
            for (int s = 0; s < 2; s++) {
                size_t r = R0 + s * 128 + warp * 16 + gid;
                uint32_t a0 = tp[r * 32 + k4 * 8 + tig];
                uint32_t a1 = tp[(r + 8) * 32 + k4 * 8 + tig];
                uint32_t a2 = tp[r * 32 + k4 * 8 + tig + 4];
                uint32_t a3 = tp[(r + 8) * 32 + k4 * 8 + tig + 4];
                #pragma unroll
                for (int n8 = 0; n8 < 8; n8++) {
                    mma_f16(C[s][n8], a0, a1, a2, a3, bf[n8].x, bf[n8].y);  // hi
                    mma_f16(C[s][n8], a0, a1, a2, a3, bf[n8].z, bf[n8].w);  // lo
                }
            }
        }
    }

    // epilogue: bias + tanh + fp16 store + stats
    __half2* toutp = (__half2*)(g_t + (size_t)mslot * BATCH * HID);
    float ssum[16], ssq[16];
    #pragma unroll
    for (int i = 0; i < 16; i++) { ssum[i] = 0.f; ssq[i] = 0.f; }

    #pragma unroll
    for (int s = 0; s < 2; s++) {
        size_t r = R0 + s * 128 + warp * 16 + gid;
        #pragma unroll
        for (int n8 = 0; n8 < 8; n8++) {
            int col = n8 * 8 + tig * 2;
            float bb0 = g_cbias[col], bb1 = g_cbias[col + 1];
            float v00 = my_tanh(C[s][n8][0] + bb0);
            float v01 = my_tanh(C[s][n8][1] + bb1);
            float v10 = my_tanh(C[s][n8][2] + bb0);
            float v11 = my_tanh(C[s][n8][3] + bb1);
            toutp[r * 32 + n8 * 4 + tig]       = __floats2half2_rn(v00, v01);
            toutp[(r + 8) * 32 + n8 * 4 + tig] = __floats2half2_rn(v10, v11);
            ssum[2 * n8]     += v00 + v10;
            ssum[2 * n8 + 1] += v01 + v11;
            ssq[2 * n8]      += v00 * v00 + v10 * v10;
            ssq[2 * n8 + 1]  += v01 * v01 + v11 * v11;
        }
    }

    #pragma unroll
    for (int i = 0; i < 16; i++) {
        ssum[i] += __shfl_xor_sync(0xffffffffu, ssum[i], 4);
        ssq[i]  += __shfl_xor_sync(0xffffffffu, ssq[i], 4);
        ssum[i] += __shfl_xor_sync(0xffffffffu, ssum[i], 8);
        ssq[i]  += __shfl_xor_sync(0xffffffffu, ssq[i], 8);
        ssum[i] += __shfl_xor_sync(0xffffffffu, ssum[i], 16);
        ssq[i]  += __shfl_xor_sync(0xffffffffu, ssq[i], 16);
    }
    if (lane < 4) {
        #pragma unroll
        for (int n8 = 0; n8 < 8; n8++) {
            int col = n8 * 8 + lane * 2;
            atomicAdd(&s_sum[col],     ssum[2 * n8]);
            atomicAdd(&s_sum[col + 1], ssum[2 * n8 + 1]);
            atomicAdd(&s_sq[col],      ssq[2 * n8]);
            atomicAdd(&s_sq[col + 1],  ssq[2 * n8 + 1]);
        }
    }
    __syncthreads();
    if (tid < 64) {
        atomicAdd(&g_sums[mslot + 1][0][tid], s_sum[tid]);
        atomicAdd(&g_sums[mslot + 1][1][tid], s_sq[tid]);
    }
}

// output: y5 = sum_{j=0..4} aff[1+j](t_j);  out = y5 @ Wout + bout
__global__ __launch_bounds__(256) void out_kernel(const float* __restrict__ Wout,
                                                  const float* __restrict__ bout,
                                                  float* __restrict__ out) {
    __shared__ float Ws[64][4];
    __shared__ float Saff[5][2][64];
    __shared__ float bb[3];
    int tid = threadIdx.x;
    if (tid < 192) Ws[tid / 3][tid % 3] = Wout[tid];
    if (tid < 3) bb[tid] = bout[tid];
    for (int i = tid; i < 5 * 128; i += 256) {
        int j = i >> 7, rest = i & 127;
        Saff[j][rest >> 6][rest & 63] = g_aff[1 + j][rest >> 6][rest & 63];
    }
    __syncthreads();

    int g = tid & 7, sub = tid >> 3;
    int cb = g * 8;
    float w[8][3];
    #pragma unroll
    for (int e = 0; e < 8; e++) {
        w[e][0] = Ws[cb + e][0];
        w[e][1] = Ws[cb + e][1];
        w[e][2] = Ws[cb + e][2];
    }

    size_t row0 = (size_t)blockIdx.x * 256;
    #pragma unroll
    for (int it = 0; it < 8; it++) {
        size_t r = row0 + it * 32 + sub;
        float y[8];
        #pragma unroll
        for (int e = 0; e < 8; e++) y[e] = 0.f;
        #pragma unroll
        for (int j = 0; j < 5; j++) {
            union { uint4 u; __half2 h2[4]; } cv;
            cv.u = ((const uint4*)(g_t + (size_t)j * BATCH * HID))[r * 8 + g];
            #pragma unroll
            for (int p = 0; p < 4; p++) {
                float2 f = __half22float2(cv.h2[p]);
                y[2 * p]     += Saff[j][0][cb + 2 * p] * f.x + Saff[j][1][cb + 2 * p];
                y[2 * p + 1] += Saff[j][0][cb + 2 * p + 1] * f.y + Saff[j][1][cb + 2 * p + 1];
            }
        }
        float p0 = 0.f, p1 = 0.f, p2 = 0.f;
        #pragma unroll
        for (int e = 0; e < 8; e++) {
            p0 += y[e] * w[e][0];
            p1 += y[e] * w[e][1];
            p2 += y[e] * w[e][2];
        }
        #pragma unroll
        for (int off = 1; off < 8; off <<= 1) {
            p0 += __shfl_xor_sync(0xffffffffu, p0, off);
            p1 += __shfl_xor_sync(0xffffffffu, p1, off);
            p2 += __shfl_xor_sync(0xffffffffu, p2, off);
        }
        if (g == 0) {
            out[r * 3 + 0] = p0 + bb[0];
            out[r * 3 + 1] = p1 + bb[1];
            out[r * 3 + 2] = p2 + bb[2];
        }
    }
}

// ---------------- launch ----------------
extern "C" void kernel_launch(void* const* d_in, const int* in_sizes, int n_in,
                              void* d_out, int out_size) {
    const float* x    = (const float*)d_in[0];
    const float* bn0g = (const float*)d_in[1];
    const float* bn0b = (const float*)d_in[2];
    const float* W0   = (const float*)d_in[3];
    const float* b0   = (const float*)d_in[4];
    const float* g0   = (const float*)d_in[5];
    const float* be0  = (const float*)d_in[6];
    const float* Wh   = (const float*)d_in[7];
    const float* bh   = (const float*)d_in[8];
    const float* gh   = (const float*)d_in[9];
    const float* beh  = (const float*)d_in[10];
    const float* Wo   = (const float*)d_in[11];
    const float* bo   = (const float*)d_in[12];
    float* out = (float*)d_out;

    zero_kernel<<<3, 256>>>();
    xstats_kernel<<<1024, 256>>>(x);
    fin_kernel<<<1, 64>>>(0, bn0g, bn0b, 4);
    k1_kernel<<<4096, 256>>>(x, W0, b0);
    fin_kernel<<<1, 64>>>(1, g0, be0, 64);

    for (int m = 1; m <= 4; m++) {
        prep_kernel<<<m * 4 + 1, 256>>>(m, Wh + (size_t)(m - 1) * 4096, bh + (m - 1) * 64);
        switch (m) {
            case 1: midk<1><<<4096, 256>>>(m); break;
            case 2: midk<2><<<4096, 256>>>(m); break;
            case 3: midk<3><<<4096, 256>>>(m); break;
            case 4: midk<4><<<4096, 256>>>(m); break;
        }
        fin_kernel<<<1, 64>>>(m + 1, gh + (m - 1) * 64, beh + (m - 1) * 64, 64);
    }
    out_kernel<<<4096, 256>>>(Wo, bo, out);
}

// round 6
// speedup vs baseline: 1.0841x; 1.0741x over previous
#include <cuda_runtime.h>
#include <cuda_fp16.h>
#include <cstdint>

#define BATCH 1048576
#define HID 64

// ---------------- device-global scratch ----------------
// t_j stored in PERMUTED word layout: storage word s = tig*8 + k4*2 + h
// holds logical half2-word w = 8*k4 + tig + 4*h   (cols 2w, 2w+1)
__device__ __half g_t[(size_t)5 * BATCH * HID];
__device__ float  g_sums[6][2][64];
__device__ float  g_aff [6][2][64];
__device__ uint4  g_Bfrag[4 * 4 * 8 * 32];   // [j][k4][n8][lane] hi(x,y)/lo(z,w)
__device__ float  g_cbias[64];
__device__ float  g_bout2[3];

// ---------------- helpers ----------------
__device__ __forceinline__ uint32_t tanh_h2(uint32_t x) {
    uint32_t r;
    asm("tanh.approx.f16x2 %0, %1;" : "=r"(r) : "r"(x));
    return r;
}
__device__ __forceinline__ uint32_t packf2h2(float lo, float hi) {
    uint32_t r;
    asm("cvt.rn.f16x2.f32 %0, %1, %2;" : "=r"(r) : "f"(hi), "f"(lo));
    return r;
}
__device__ __forceinline__ float2 h2f2(uint32_t h) {
    __half2 v = *(__half2*)&h;
    return __half22float2(v);
}
__device__ __forceinline__ void mma_f16(float c[4],
                                        uint32_t a0, uint32_t a1, uint32_t a2, uint32_t a3,
                                        uint32_t b0, uint32_t b1) {
    asm volatile(
        "mma.sync.aligned.m16n8k16.row.col.f32.f16.f16.f32 "
        "{%0,%1,%2,%3}, {%4,%5,%6,%7}, {%8,%9}, {%0,%1,%2,%3};\n"
        : "+f"(c[0]), "+f"(c[1]), "+f"(c[2]), "+f"(c[3])
        : "r"(a0), "r"(a1), "r"(a2), "r"(a3), "r"(b0), "r"(b1));
}
__device__ __forceinline__ uint32_t pack_h2(float a, float b) {
    __half2 h = __floats2half2_rn(a, b);
    return *(uint32_t*)&h;
}
// logical word for storage word s (0..31)
__device__ __forceinline__ int wof(int s) {
    return 8 * ((s & 7) >> 1) + (s >> 3) + 4 * (s & 1);
}

// ---------------- small kernels ----------------
__global__ void zero_kernel() {
    int t = threadIdx.x + blockIdx.x * blockDim.x;
    if (t < 6 * 2 * 64) ((float*)g_sums)[t] = 0.0f;
}

__global__ __launch_bounds__(256) void xstats_kernel(const float* __restrict__ x) {
    __shared__ float sm[8];
    int tid = threadIdx.x;
    if (tid < 8) sm[tid] = 0.0f;
    __syncthreads();
    float s[4] = {0.f, 0.f, 0.f, 0.f}, q[4] = {0.f, 0.f, 0.f, 0.f};
    const float4* x4 = (const float4*)x;
    size_t base = (size_t)blockIdx.x * 256 + tid;
    #pragma unroll
    for (int i = 0; i < 4; i++) {
        float4 v = x4[base + (size_t)i * 262144];
        s[0] += v.x; q[0] += v.x * v.x;
        s[1] += v.y; q[1] += v.y * v.y;
        s[2] += v.z; q[2] += v.z * v.z;
        s[3] += v.w; q[3] += v.w * v.w;
    }
    #pragma unroll
    for (int k = 0; k < 4; k++)
        for (int off = 16; off; off >>= 1) {
            s[k] += __shfl_xor_sync(0xffffffffu, s[k], off);
            q[k] += __shfl_xor_sync(0xffffffffu, q[k], off);
        }
    if ((tid & 31) == 0) {
        #pragma unroll
        for (int k = 0; k < 4; k++) {
            atomicAdd(&sm[k], s[k]);
            atomicAdd(&sm[4 + k], q[k]);
        }
    }
    __syncthreads();
    if (tid < 8) atomicAdd(&g_sums[0][tid >> 2][tid & 3], sm[tid]);
}

__global__ void fin_kernel(int idx, const float* __restrict__ gamma,
                           const float* __restrict__ beta, int count) {
    int t = threadIdx.x;
    if (t >= count) return;
    const float invN = 1.0f / 1048576.0f;
    float mu  = g_sums[idx][0][t] * invN;
    float var = g_sums[idx][1][t] * invN - mu * mu;
    float sc = gamma[t] * rsqrtf(var + 1e-5f);
    g_aff[idx][0][t] = sc;
    g_aff[idx][1][t] = beta[t] - mu * sc;
}

// pre-pack Weff_{j} = diag(sc_{j+1}) @ W into mma B-fragment layout (hi/lo fp16),
// plus combined bias c[n] = b[n] + sum_j sum_k sh_{j+1}[k] W[k][n]
__global__ void prep_kernel(int m, const float* __restrict__ W, const float* __restrict__ b) {
    int blk = blockIdx.x;
    if (blk == m * 4) {
        int n = threadIdx.x;
        if (n < 64) {
            float acc = b[n];
            for (int j = 0; j < m; j++)
                for (int k = 0; k < 64; k++)
                    acc += g_aff[1 + j][1][k] * W[k * 64 + n];
            g_cbias[n] = acc;
        }
        return;
    }
    int j = blk >> 2, k4 = blk & 3;
    int t = threadIdx.x;
    int n8 = t >> 5, lane = t & 31, gid = lane >> 2, tig = lane & 3;
    int n = n8 * 8 + gid;
    int kb = k4 * 16 + 2 * tig;
    float w0 = g_aff[1 + j][0][kb]     * W[kb * 64 + n];
    float w1 = g_aff[1 + j][0][kb + 1] * W[(kb + 1) * 64 + n];
    float w8 = g_aff[1 + j][0][kb + 8] * W[(kb + 8) * 64 + n];
    float w9 = g_aff[1 + j][0][kb + 9] * W[(kb + 9) * 64 + n];
    __half h0 = __float2half_rn(w0), h1 = __float2half_rn(w1);
    __half h8 = __float2half_rn(w8), h9 = __float2half_rn(w9);
    uint4 v;
    {
        __half2 p0 = __halves2half2(h0, h1); v.x = *(uint32_t*)&p0;
        __half2 p1 = __halves2half2(h8, h9); v.y = *(uint32_t*)&p1;
    }
    v.z = pack_h2(w0 - __half2float(h0), w1 - __half2float(h1));
    v.w = pack_h2(w8 - __half2float(h8), w9 - __half2float(h9));
    g_Bfrag[((j * 4 + k4) * 8 + n8) * 32 + lane] = v;
}

// bout2[k] = bout[k] + sum_c (sum_j sh_j[c]) * Wout[c][k]
__global__ void prepout_kernel(const float* __restrict__ Wout, const float* __restrict__ bout) {
    __shared__ float acc[3];
    int c = threadIdx.x;
    if (c < 3) acc[c] = bout[c];
    __syncthreads();
    if (c < 64) {
        float sh = 0.f;
        #pragma unroll
        for (int j = 0; j < 5; j++) sh += g_aff[1 + j][1][c];
        atomicAdd(&acc[0], sh * Wout[c * 3 + 0]);
        atomicAdd(&acc[1], sh * Wout[c * 3 + 1]);
        atomicAdd(&acc[2], sh * Wout[c * 3 + 2]);
    }
    __syncthreads();
    if (c < 3) g_bout2[c] = acc[c];
}

// first layer: t0 = tanh(bn0(x) @ W0 + b0); stats -> g_sums[1]. Permuted-layout store.
__global__ __launch_bounds__(256) void k1_kernel(const float* __restrict__ x,
                                                 const float* __restrict__ W0,
                                                 const float* __restrict__ b0) {
    __shared__ float Ws[4][64];
    __shared__ float s_sum[64], s_sq[64];
    __shared__ float affs[4], affb[4];
    int tid = threadIdx.x;
    if (tid < 256) Ws[tid >> 6][tid & 63] = W0[tid];
    if (tid < 64) { s_sum[tid] = 0.f; s_sq[tid] = 0.f; }
    if (tid < 4) { affs[tid] = g_aff[0][0][tid]; affb[tid] = g_aff[0][1][tid]; }
    __syncthreads();

    int q = tid & 7, sub = tid >> 3;
    int cols[8];
    #pragma unroll
    for (int e = 0; e < 4; e++) {
        int w = wof(q * 4 + e);
        cols[2 * e] = 2 * w; cols[2 * e + 1] = 2 * w + 1;
    }
    float wk0[8], wk1[8], wk2[8], wk3[8], bb[8];
    #pragma unroll
    for (int i = 0; i < 8; i++) {
        wk0[i] = Ws[0][cols[i]]; wk1[i] = Ws[1][cols[i]];
        wk2[i] = Ws[2][cols[i]]; wk3[i] = Ws[3][cols[i]];
        bb[i] = b0[cols[i]];
    }
    float a0s = affs[0], a1s = affs[1], a2s = affs[2], a3s = affs[3];
    float a0b = affb[0], a1b = affb[1], a2b = affb[2], a3b = affb[3];
    float s[8], qq[8];
    #pragma unroll
    for (int i = 0; i < 8; i++) { s[i] = 0.f; qq[i] = 0.f; }

    size_t row0 = (size_t)blockIdx.x * 256;
    const float4* x4 = (const float4*)x;
    uint4* outp = (uint4*)g_t;

    #pragma unroll
    for (int it = 0; it < 8; it++) {
        size_t r = row0 + it * 32 + sub;
        float4 xv = x4[r];
        float h0 = xv.x * a0s + a0b;
        float h1 = xv.y * a1s + a1b;
        float h2 = xv.z * a2s + a2b;
        float h3 = xv.w * a3s + a3b;
        uint32_t wrd[4];
        #pragma unroll
        for (int e = 0; e < 4; e++) {
            float z0 = bb[2*e]   + h0*wk0[2*e]   + h1*wk1[2*e]   + h2*wk2[2*e]   + h3*wk3[2*e];
            float z1 = bb[2*e+1] + h0*wk0[2*e+1] + h1*wk1[2*e+1] + h2*wk2[2*e+1] + h3*wk3[2*e+1];
            wrd[e] = tanh_h2(packf2h2(z0, z1));
            float2 f = h2f2(wrd[e]);
            s[2*e] += f.x;  qq[2*e] += f.x * f.x;
            s[2*e+1] += f.y; qq[2*e+1] += f.y * f.y;
        }
        outp[r * 8 + q] = make_uint4(wrd[0], wrd[1], wrd[2], wrd[3]);
    }

    #pragma unroll
    for (int i = 0; i < 8; i++) {
        s[i]  += __shfl_xor_sync(0xffffffffu, s[i], 8);
        qq[i] += __shfl_xor_sync(0xffffffffu, qq[i], 8);
        s[i]  += __shfl_xor_sync(0xffffffffu, s[i], 16);
        qq[i] += __shfl_xor_sync(0xffffffffu, qq[i], 16);
    }
    if ((tid & 24) == 0) {
        #pragma unroll
        for (int i = 0; i < 8; i++) {
            atomicAdd(&s_sum[cols[i]], s[i]);
            atomicAdd(&s_sq[cols[i]], qq[i]);
        }
    }
    __syncthreads();
    if (tid < 64) {
        atomicAdd(&g_sums[1][0][tid], s_sum[tid]);
        atomicAdd(&g_sums[1][1][tid], s_sq[tid]);
    }
}

// mid layer m: z = sum_{j<m} t_j @ Weff_j + c; t_m = tanh(z); stats -> g_sums[m+1]
// 256 threads (8 warps), 256 rows/CTA (s=2 x 128), grid 4096. No mainloop syncs.
template <int M>
__global__ void __launch_bounds__(256, 2) midk(int mslot) {
    __shared__ float s_sum[64], s_sq[64];
    int tid = threadIdx.x, warp = tid >> 5, lane = tid & 31;
    int gid = lane >> 2, tig = lane & 3;
    if (tid < 64) { s_sum[tid] = 0.f; s_sq[tid] = 0.f; }

    float C[2][8][4];
    #pragma unroll
    for (int s = 0; s < 2; s++)
        #pragma unroll
        for (int n8 = 0; n8 < 8; n8++)
            #pragma unroll
            for (int e = 0; e < 4; e++) C[s][n8][e] = 0.f;

    size_t R0 = (size_t)blockIdx.x * 256;
    size_t rb[2] = { R0 + warp * 16 + gid, R0 + 128 + warp * 16 + gid };

    #pragma unroll
    for (int j = 0; j < M; j++) {
        const uint4* tp = (const uint4*)(g_t + (size_t)j * BATCH * HID);
        // A: per (s, rowhalf): 2 LDG.128 cover all k4 (permuted layout)
        uint4 A[2][2][2];
        #pragma unroll
        for (int s = 0; s < 2; s++)
            #pragma unroll
            for (int rh = 0; rh < 2; rh++) {
                size_t base = (rb[s] + rh * 8) * 8 + tig * 2;
                A[s][rh][0] = tp[base];
                A[s][rh][1] = tp[base + 1];
            }
        #pragma unroll
        for (int k4 = 0; k4 < 4; k4++) {
            #pragma unroll
            for (int n8 = 0; n8 < 8; n8++) {
                uint4 bf = g_Bfrag[((j * 4 + k4) * 8 + n8) * 32 + lane];
                #pragma unroll
                for (int s = 0; s < 2; s++) {
                    uint4 lo = A[s][0][k4 >> 1];
                    uint4 hi = A[s][1][k4 >> 1];
                    uint32_t a0 = (k4 & 1) ? lo.z : lo.x;
                    uint32_t a2 = (k4 & 1) ? lo.w : lo.y;
                    uint32_t a1 = (k4 & 1) ? hi.z : hi.x;
                    uint32_t a3 = (k4 & 1) ? hi.w : hi.y;
                    mma_f16(C[s][n8], a0, a1, a2, a3, bf.x, bf.y);  // hi
                    mma_f16(C[s][n8], a0, a1, a2, a3, bf.z, bf.w);  // lo
                }
            }
        }
    }

    // ---- epilogue: bias + tanh.f16x2 + packed store (2 STG.128/row) + stats ----
    uint4* toutp = (uint4*)(g_t + (size_t)mslot * BATCH * HID);
    float ssum[16], ssq[16];
    #pragma unroll
    for (int i = 0; i < 16; i++) { ssum[i] = 0.f; ssq[i] = 0.f; }

    #pragma unroll
    for (int s = 0; s < 2; s++) {
        uint32_t w0[8], w1[8];   // row gid / row gid+8, storage words tig*8 + n8
        #pragma unroll
        for (int n8 = 0; n8 < 8; n8++) {
            int col = n8 * 8 + tig * 2;
            float b0 = g_cbias[col], b1 = g_cbias[col + 1];
            uint32_t h0 = tanh_h2(packf2h2(C[s][n8][0] + b0, C[s][n8][1] + b1));
            uint32_t h1 = tanh_h2(packf2h2(C[s][n8][2] + b0, C[s][n8][3] + b1));
            w0[n8] = h0; w1[n8] = h1;
            float2 f0 = h2f2(h0), f1 = h2f2(h1);
            ssum[2*n8]   += f0.x + f1.x;  ssq[2*n8]   += f0.x*f0.x + f1.x*f1.x;
            ssum[2*n8+1] += f0.y + f1.y;  ssq[2*n8+1] += f0.y*f0.y + f1.y*f1.y;
        }
        size_t r = rb[s];
        toutp[r * 8 + tig * 2]           = make_uint4(w0[0], w0[1], w0[2], w0[3]);
        toutp[r * 8 + tig * 2 + 1]       = make_uint4(w0[4], w0[5], w0[6], w0[7]);
        toutp[(r + 8) * 8 + tig * 2]     = make_uint4(w1[0], w1[1], w1[2], w1[3]);
        toutp[(r + 8) * 8 + tig * 2 + 1] = make_uint4(w1[4], w1[5], w1[6], w1[7]);
    }

    #pragma unroll
    for (int i = 0; i < 16; i++) {
        ssum[i] += __shfl_xor_sync(0xffffffffu, ssum[i], 4);
        ssq[i]  += __shfl_xor_sync(0xffffffffu, ssq[i], 4);
        ssum[i] += __shfl_xor_sync(0xffffffffu, ssum[i], 8);
        ssq[i]  += __shfl_xor_sync(0xffffffffu, ssq[i], 8);
        ssum[i] += __shfl_xor_sync(0xffffffffu, ssum[i], 16);
        ssq[i]  += __shfl_xor_sync(0xffffffffu, ssq[i], 16);
    }
    __syncthreads();
    if (lane < 4) {
        #pragma unroll
        for (int n8 = 0; n8 < 8; n8++) {
            int col = n8 * 8 + lane * 2;
            atomicAdd(&s_sum[col],     ssum[2 * n8]);
            atomicAdd(&s_sum[col + 1], ssum[2 * n8 + 1]);
            atomicAdd(&s_sq[col],      ssq[2 * n8]);
            atomicAdd(&s_sq[col + 1],  ssq[2 * n8 + 1]);
        }
    }
    __syncthreads();
    if (tid < 64) {
        atomicAdd(&g_sums[mslot + 1][0][tid], s_sum[tid]);
        atomicAdd(&g_sums[mslot + 1][1][tid], s_sq[tid]);
    }
}

// out[r] = (sum_j sc_j .* t_j[r]) @ Wout + bout2   (shifts folded into bout2)
__global__ __launch_bounds__(256, 2) void out_kernel(const float* __restrict__ Wout,
                                                     float* __restrict__ out) {
    int tid = threadIdx.x;
    int g = tid & 7, sub = tid >> 3;
    int cols[8];
    #pragma unroll
    for (int e = 0; e < 4; e++) {
        int w = wof(g * 4 + e);
        cols[2 * e] = 2 * w; cols[2 * e + 1] = 2 * w + 1;
    }
    float wv[8][3];
    #pragma unroll
    for (int i = 0; i < 8; i++) {
        wv[i][0] = Wout[cols[i] * 3 + 0];
        wv[i][1] = Wout[cols[i] * 3 + 1];
        wv[i][2] = Wout[cols[i] * 3 + 2];
    }
    float scr[5][8];
    #pragma unroll
    for (int j = 0; j < 5; j++)
        #pragma unroll
        for (int i = 0; i < 8; i++) scr[j][i] = g_aff[1 + j][0][cols[i]];
    float bo0 = g_bout2[0], bo1 = g_bout2[1], bo2 = g_bout2[2];

    size_t row0 = (size_t)blockIdx.x * 256;
    #pragma unroll
    for (int it = 0; it < 8; it++) {
        size_t r = row0 + it * 32 + sub;
        float y[8];
        #pragma unroll
        for (int i = 0; i < 8; i++) y[i] = 0.f;
        #pragma unroll
        for (int j = 0; j < 5; j++) {
            uint4 cv = ((const uint4*)(g_t + (size_t)j * BATCH * HID))[r * 8 + g];
            uint32_t ws[4] = {cv.x, cv.y, cv.z, cv.w};
            #pragma unroll
            for (int e = 0; e < 4; e++) {
                float2 f = h2f2(ws[e]);
                y[2 * e]     += scr[j][2 * e] * f.x;
                y[2 * e + 1] += scr[j][2 * e + 1] * f.y;
            }
        }
        float p0 = 0.f, p1 = 0.f, p2 = 0.f;
        #pragma unroll
        for (int i = 0; i < 8; i++) {
            p0 += y[i] * wv[i][0];
            p1 += y[i] * wv[i][1];
            p2 += y[i] * wv[i][2];
        }
        #pragma unroll
        for (int off = 1; off < 8; off <<= 1) {
            p0 += __shfl_xor_sync(0xffffffffu, p0, off);
            p1 += __shfl_xor_sync(0xffffffffu, p1, off);
            p2 += __shfl_xor_sync(0xffffffffu, p2, off);
        }
        if (g == 0) {
            out[r * 3 + 0] = p0 + bo0;
            out[r * 3 + 1] = p1 + bo1;
            out[r * 3 + 2] = p2 + bo2;
        }
    }
}

// ---------------- launch ----------------
extern "C" void kernel_launch(void* const* d_in, const int* in_sizes, int n_in,
                              void* d_out, int out_size) {
    const float* x    = (const float*)d_in[0];
    const float* bn0g = (const float*)d_in[1];
    const float* bn0b = (const float*)d_in[2];
    const float* W0   = (const float*)d_in[3];
    const float* b0   = (const float*)d_in[4];
    const float* g0   = (const float*)d_in[5];
    const float* be0  = (const float*)d_in[6];
    const float* Wh   = (const float*)d_in[7];
    const float* bh   = (const float*)d_in[8];
    const float* gh   = (const float*)d_in[9];
    const float* beh  = (const float*)d_in[10];
    const float* Wo   = (const float*)d_in[11];
    const float* bo   = (const float*)d_in[12];
    float* out = (float*)d_out;

    zero_kernel<<<3, 256>>>();
    xstats_kernel<<<1024, 256>>>(x);
    fin_kernel<<<1, 64>>>(0, bn0g, bn0b, 4);
    k1_kernel<<<4096, 256>>>(x, W0, b0);
    fin_kernel<<<1, 64>>>(1, g0, be0, 64);

    for (int m = 1; m <= 4; m++) {
        prep_kernel<<<m * 4 + 1, 256>>>(m, Wh + (size_t)(m - 1) * 4096, bh + (m - 1) * 64);
        switch (m) {
            case 1: midk<1><<<4096, 256>>>(m); break;
            case 2: midk<2><<<4096, 256>>>(m); break;
            case 3: midk<3><<<4096, 256>>>(m); break;
            case 4: midk<4><<<4096, 256>>>(m); break;
        }
        fin_kernel<<<1, 64>>>(m + 1, gh + (m - 1) * 64, beh + (m - 1) * 64, 64);
    }
    prepout_kernel<<<1, 64>>>(Wo, bo);
    out_kernel<<<4096, 256>>>(Wo, out);
}

// round 8
// speedup vs baseline: 1.6874x; 1.5565x over previous
#include <cuda_runtime.h>
#include <cuda_fp16.h>
#include <cstdint>

#define BATCH 1048576
#define HID 64

// ---------------- device-global scratch ----------------
// t_j stored in PERMUTED word layout (fragment-native, see midk A-loads)
__device__ __half g_t[(size_t)5 * BATCH * HID];
__device__ float  g_sums[6][2][64];
__device__ float  g_aff [6][2][64];
__device__ uint4  g_Bfrag[4 * 4 * 8 * 32];   // [j][k4][n8][lane] hi(x,y)/lo(z,w)
__device__ uint4  g_OBfrag[5 * 4 * 32];      // [j][k4][lane] out-tile frags (N=8, cols 0..2 real)
__device__ float  g_cbias[64];
__device__ float  g_bout2[3];
__device__ float  g_pout[(size_t)3 * BATCH]; // partial out = sum_{j<4} t_j @ (sc_j*Wout)

// ---------------- helpers ----------------
__device__ __forceinline__ uint32_t tanh_h2(uint32_t x) {
    uint32_t r;
    asm("tanh.approx.f16x2 %0, %1;" : "=r"(r) : "r"(x));
    return r;
}
__device__ __forceinline__ uint32_t packf2h2(float lo, float hi) {
    uint32_t r;
    asm("cvt.rn.f16x2.f32 %0, %1, %2;" : "=r"(r) : "f"(hi), "f"(lo));
    return r;
}
__device__ __forceinline__ float2 h2f2(uint32_t h) {
    __half2 v = *(__half2*)&h;
    return __half22float2(v);
}
__device__ __forceinline__ void mma_f16(float c[4],
                                        uint32_t a0, uint32_t a1, uint32_t a2, uint32_t a3,
                                        uint32_t b0, uint32_t b1) {
    asm volatile(
        "mma.sync.aligned.m16n8k16.row.col.f32.f16.f16.f32 "
        "{%0,%1,%2,%3}, {%4,%5,%6,%7}, {%8,%9}, {%0,%1,%2,%3};\n"
        : "+f"(c[0]), "+f"(c[1]), "+f"(c[2]), "+f"(c[3])
        : "r"(a0), "r"(a1), "r"(a2), "r"(a3), "r"(b0), "r"(b1));
}
__device__ __forceinline__ uint32_t pack_h2(float a, float b) {
    __half2 h = __floats2half2_rn(a, b);
    return *(uint32_t*)&h;
}
// logical half2-word for storage word s (0..31)
__device__ __forceinline__ int wof(int s) {
    return 8 * ((s & 7) >> 1) + (s >> 3) + 4 * (s & 1);
}

// ---------------- small kernels ----------------
__global__ void zero_kernel() {
    int t = threadIdx.x + blockIdx.x * blockDim.x;
    if (t < 6 * 2 * 64) ((float*)g_sums)[t] = 0.0f;
}

__global__ __launch_bounds__(256) void xstats_kernel(const float* __restrict__ x) {
    __shared__ float sm[8];
    int tid = threadIdx.x;
    if (tid < 8) sm[tid] = 0.0f;
    __syncthreads();
    float s[4] = {0.f, 0.f, 0.f, 0.f}, q[4] = {0.f, 0.f, 0.f, 0.f};
    const float4* x4 = (const float4*)x;
    size_t base = (size_t)blockIdx.x * 256 + tid;
    #pragma unroll
    for (int i = 0; i < 4; i++) {
        float4 v = x4[base + (size_t)i * 262144];
        s[0] += v.x; q[0] += v.x * v.x;
        s[1] += v.y; q[1] += v.y * v.y;
        s[2] += v.z; q[2] += v.z * v.z;
        s[3] += v.w; q[3] += v.w * v.w;
    }
    #pragma unroll
    for (int k = 0; k < 4; k++)
        for (int off = 16; off; off >>= 1) {
            s[k] += __shfl_xor_sync(0xffffffffu, s[k], off);
            q[k] += __shfl_xor_sync(0xffffffffu, q[k], off);
        }
    if ((tid & 31) == 0) {
        #pragma unroll
        for (int k = 0; k < 4; k++) {
            atomicAdd(&sm[k], s[k]);
            atomicAdd(&sm[4 + k], q[k]);
        }
    }
    __syncthreads();
    if (tid < 8) atomicAdd(&g_sums[0][tid >> 2][tid & 3], sm[tid]);
}

__global__ void fin_kernel(int idx, const float* __restrict__ gamma,
                           const float* __restrict__ beta, int count) {
    int t = threadIdx.x;
    if (t >= count) return;
    const float invN = 1.0f / 1048576.0f;
    float mu  = g_sums[idx][0][t] * invN;
    float var = g_sums[idx][1][t] * invN - mu * mu;
    float sc = gamma[t] * rsqrtf(var + 1e-5f);
    g_aff[idx][0][t] = sc;
    g_aff[idx][1][t] = beta[t] - mu * sc;
}

// prep for mid layer m:
//  blocks [0, m*4)        : Weff_{j} = diag(sc_{j+1}) @ W  -> g_Bfrag (hi/lo fp16)
//  block  m*4             : combined bias
//  blocks (m*4, m*4+4]    : OBfrag[m-1] = frags of diag(sc_{m-1-slot}...)  out-tile for layer m-1
__global__ void prep_kernel(int m, const float* __restrict__ W, const float* __restrict__ b,
                            const float* __restrict__ Wout) {
    int blk = blockIdx.x;
    int t = threadIdx.x;
    if (blk == m * 4) {
        int n = t;
        if (n < 64) {
            float acc = b[n];
            for (int j = 0; j < m; j++)
                for (int k = 0; k < 64; k++)
                    acc += g_aff[1 + j][1][k] * W[k * 64 + n];
            g_cbias[n] = acc;
        }
        return;
    }
    if (blk > m * 4) {
        // OBfrag for layer jo = m-1 (scales g_aff[m][0] just produced by fin)
        if (t >= 32) return;
        int k4 = blk - m * 4 - 1;
        int jo = m - 1;
        int lane = t, gid = lane >> 2, tig = lane & 3;
        int n = gid;              // out col (0..7), only 0..2 real
        int kb = k4 * 16 + 2 * tig;
        float w0 = 0.f, w1 = 0.f, w8 = 0.f, w9 = 0.f;
        if (n < 3) {
            w0 = g_aff[1 + jo][0][kb]     * Wout[kb * 3 + n];
            w1 = g_aff[1 + jo][0][kb + 1] * Wout[(kb + 1) * 3 + n];
            w8 = g_aff[1 + jo][0][kb + 8] * Wout[(kb + 8) * 3 + n];
            w9 = g_aff[1 + jo][0][kb + 9] * Wout[(kb + 9) * 3 + n];
        }
        __half h0 = __float2half_rn(w0), h1 = __float2half_rn(w1);
        __half h8 = __float2half_rn(w8), h9 = __float2half_rn(w9);
        uint4 v;
        { __half2 p0 = __halves2half2(h0, h1); v.x = *(uint32_t*)&p0;
          __half2 p1 = __halves2half2(h8, h9); v.y = *(uint32_t*)&p1; }
        v.z = pack_h2(w0 - __half2float(h0), w1 - __half2float(h1));
        v.w = pack_h2(w8 - __half2float(h8), w9 - __half2float(h9));
        g_OBfrag[(jo * 4 + k4) * 32 + lane] = v;
        return;
    }
    int j = blk >> 2, k4 = blk & 3;
    int n8 = t >> 5, lane = t & 31, gid = lane >> 2, tig = lane & 3;
    int n = n8 * 8 + gid;
    int kb = k4 * 16 + 2 * tig;
    float w0 = g_aff[1 + j][0][kb]     * W[kb * 64 + n];
    float w1 = g_aff[1 + j][0][kb + 1] * W[(kb + 1) * 64 + n];
    float w8 = g_aff[1 + j][0][kb + 8] * W[(kb + 8) * 64 + n];
    float w9 = g_aff[1 + j][0][kb + 9] * W[(kb + 9) * 64 + n];
    __half h0 = __float2half_rn(w0), h1 = __float2half_rn(w1);
    __half h8 = __float2half_rn(w8), h9 = __float2half_rn(w9);
    uint4 v;
    { __half2 p0 = __halves2half2(h0, h1); v.x = *(uint32_t*)&p0;
      __half2 p1 = __halves2half2(h8, h9); v.y = *(uint32_t*)&p1; }
    v.z = pack_h2(w0 - __half2float(h0), w1 - __half2float(h1));
    v.w = pack_h2(w8 - __half2float(h8), w9 - __half2float(h9));
    g_Bfrag[((j * 4 + k4) * 8 + n8) * 32 + lane] = v;
}

// after fin(5): OBfrag[4] (blocks 0-3) + bout2 (block 4)
__global__ void prepout_kernel(const float* __restrict__ Wout, const float* __restrict__ bout) {
    int blk = blockIdx.x, t = threadIdx.x;
    if (blk == 4) {
        __shared__ float acc[3];
        if (t < 3) acc[t] = bout[t];
        __syncthreads();
        if (t < 64) {
            float sh = 0.f;
            #pragma unroll
            for (int j = 0; j < 5; j++) sh += g_aff[1 + j][1][t];
            atomicAdd(&acc[0], sh * Wout[t * 3 + 0]);
            atomicAdd(&acc[1], sh * Wout[t * 3 + 1]);
            atomicAdd(&acc[2], sh * Wout[t * 3 + 2]);
        }
        __syncthreads();
        if (t < 3) g_bout2[t] = acc[t];
        return;
    }
    if (t >= 32) return;
    int k4 = blk;
    int lane = t, gid = lane >> 2, tig = lane & 3;
    int n = gid;
    int kb = k4 * 16 + 2 * tig;
    float w0 = 0.f, w1 = 0.f, w8 = 0.f, w9 = 0.f;
    if (n < 3) {
        w0 = g_aff[5][0][kb]     * Wout[kb * 3 + n];
        w1 = g_aff[5][0][kb + 1] * Wout[(kb + 1) * 3 + n];
        w8 = g_aff[5][0][kb + 8] * Wout[(kb + 8) * 3 + n];
        w9 = g_aff[5][0][kb + 9] * Wout[(kb + 9) * 3 + n];
    }
    __half h0 = __float2half_rn(w0), h1 = __float2half_rn(w1);
    __half h8 = __float2half_rn(w8), h9 = __float2half_rn(w9);
    uint4 v;
    { __half2 p0 = __halves2half2(h0, h1); v.x = *(uint32_t*)&p0;
      __half2 p1 = __halves2half2(h8, h9); v.y = *(uint32_t*)&p1; }
    v.z = pack_h2(w0 - __half2float(h0), w1 - __half2float(h1));
    v.w = pack_h2(w8 - __half2float(h8), w9 - __half2float(h9));
    g_OBfrag[(4 * 4 + k4) * 32 + lane] = v;
}

// first layer: t0 = tanh(bn0(x) @ W0 + b0); stats -> g_sums[1]. 128 rows/CTA.
__global__ __launch_bounds__(256) void k1_kernel(const float* __restrict__ x,
                                                 const float* __restrict__ W0,
                                                 const float* __restrict__ b0) {
    __shared__ float Ws[4][64];
    __shared__ float s_sum[64], s_sq[64];
    __shared__ float affs[4], affb[4];
    int tid = threadIdx.x;
    if (tid < 256) Ws[tid >> 6][tid & 63] = W0[tid];
    if (tid < 64) { s_sum[tid] = 0.f; s_sq[tid] = 0.f; }
    if (tid < 4) { affs[tid] = g_aff[0][0][tid]; affb[tid] = g_aff[0][1][tid]; }
    __syncthreads();

    int q = tid & 7, sub = tid >> 3;
    int cols[8];
    #pragma unroll
    for (int e = 0; e < 4; e++) {
        int w = wof(q * 4 + e);
        cols[2 * e] = 2 * w; cols[2 * e + 1] = 2 * w + 1;
    }
    float wk0[8], wk1[8], wk2[8], wk3[8], bb[8];
    #pragma unroll
    for (int i = 0; i < 8; i++) {
        wk0[i] = Ws[0][cols[i]]; wk1[i] = Ws[1][cols[i]];
        wk2[i] = Ws[2][cols[i]]; wk3[i] = Ws[3][cols[i]];
        bb[i] = b0[cols[i]];
    }
    float a0s = affs[0], a1s = affs[1], a2s = affs[2], a3s = affs[3];
    float a0b = affb[0], a1b = affb[1], a2b = affb[2], a3b = affb[3];
    float s[8], qq[8];
    #pragma unroll
    for (int i = 0; i < 8; i++) { s[i] = 0.f; qq[i] = 0.f; }

    size_t row0 = (size_t)blockIdx.x * 128;
    const float4* x4 = (const float4*)x;
    uint4* outp = (uint4*)g_t;

    #pragma unroll
    for (int it = 0; it < 4; it++) {
        size_t r = row0 + it * 32 + sub;
        float4 xv = x4[r];
        float h0 = xv.x * a0s + a0b;
        float h1 = xv.y * a1s + a1b;
        float h2 = xv.z * a2s + a2b;
        float h3 = xv.w * a3s + a3b;
        uint32_t wrd[4];
        #pragma unroll
        for (int e = 0; e < 4; e++) {
            float z0 = bb[2*e]   + h0*wk0[2*e]   + h1*wk1[2*e]   + h2*wk2[2*e]   + h3*wk3[2*e];
            float z1 = bb[2*e+1] + h0*wk0[2*e+1] + h1*wk1[2*e+1] + h2*wk2[2*e+1] + h3*wk3[2*e+1];
            wrd[e] = tanh_h2(packf2h2(z0, z1));
            float2 f = h2f2(wrd[e]);
            s[2*e] += f.x;  qq[2*e] += f.x * f.x;
            s[2*e+1] += f.y; qq[2*e+1] += f.y * f.y;
        }
        outp[r * 8 + q] = make_uint4(wrd[0], wrd[1], wrd[2], wrd[3]);
    }

    #pragma unroll
    for (int i = 0; i < 8; i++) {
        s[i]  += __shfl_xor_sync(0xffffffffu, s[i], 8);
        qq[i] += __shfl_xor_sync(0xffffffffu, qq[i], 8);
        s[i]  += __shfl_xor_sync(0xffffffffu, s[i], 16);
        qq[i] += __shfl_xor_sync(0xffffffffu, qq[i], 16);
    }
    if ((tid & 24) == 0) {
        #pragma unroll
        for (int i = 0; i < 8; i++) {
            atomicAdd(&s_sum[cols[i]], s[i]);
            atomicAdd(&s_sq[cols[i]], qq[i]);
        }
    }
    __syncthreads();
    if (tid < 64) {
        atomicAdd(&g_sums[1][0][tid], s_sum[tid]);
        atomicAdd(&g_sums[1][1][tid], s_sq[tid]);
    }
}

// mid layer m: z = sum_{j<m} t_j @ Weff_j + c; t_m = tanh(z); stats -> g_sums[m+1]
// FUSE (m==4): also accumulate partial out = sum_{j<4} t_j @ (sc_j*Wout) -> g_pout
template <int M, bool FUSE>
__global__ void __launch_bounds__(256, 2) midk(int mslot) {
    __shared__ float s_sum[64], s_sq[64];
    int tid = threadIdx.x, warp = tid >> 5, lane = tid & 31;
    int gid = lane >> 2, tig = lane & 3;
    if (tid < 64) { s_sum[tid] = 0.f; s_sq[tid] = 0.f; }

    float C[2][8][4];
    #pragma unroll
    for (int s = 0; s < 2; s++)
        #pragma unroll
        for (int n8 = 0; n8 < 8; n8++)
            #pragma unroll
            for (int e = 0; e < 4; e++) C[s][n8][e] = 0.f;
    float Co[2][4];
    if (FUSE) {
        #pragma unroll
        for (int s = 0; s < 2; s++)
            #pragma unroll
            for (int e = 0; e < 4; e++) Co[s][e] = 0.f;
    }

    size_t R0 = (size_t)blockIdx.x * 256;
    size_t rb[2] = { R0 + warp * 16 + gid, R0 + 128 + warp * 16 + gid };

    #pragma unroll
    for (int j = 0; j < M; j++) {
        const uint4* tp = (const uint4*)(g_t + (size_t)j * BATCH * HID);
        uint4 A[2][2][2];
        #pragma unroll
        for (int s = 0; s < 2; s++)
            #pragma unroll
            for (int rh = 0; rh < 2; rh++) {
                size_t base = (rb[s] + rh * 8) * 8 + tig * 2;
                A[s][rh][0] = tp[base];
                A[s][rh][1] = tp[base + 1];
            }
        #pragma unroll
        for (int k4 = 0; k4 < 4; k4++) {
            #pragma unroll
            for (int n8 = 0; n8 < 8; n8++) {
                uint4 bf = g_Bfrag[((j * 4 + k4) * 8 + n8) * 32 + lane];
                #pragma unroll
                for (int s = 0; s < 2; s++) {
                    uint4 lo = A[s][0][k4 >> 1];
                    uint4 hi = A[s][1][k4 >> 1];
                    uint32_t a0 = (k4 & 1) ? lo.z : lo.x;
                    uint32_t a2 = (k4 & 1) ? lo.w : lo.y;
                    uint32_t a1 = (k4 & 1) ? hi.z : hi.x;
                    uint32_t a3 = (k4 & 1) ? hi.w : hi.y;
                    mma_f16(C[s][n8], a0, a1, a2, a3, bf.x, bf.y);  // hi
                    mma_f16(C[s][n8], a0, a1, a2, a3, bf.z, bf.w);  // lo
                }
            }
            if (FUSE) {
                uint4 of = g_OBfrag[(j * 4 + k4) * 32 + lane];
                #pragma unroll
                for (int s = 0; s < 2; s++) {
                    uint4 lo = A[s][0][k4 >> 1];
                    uint4 hi = A[s][1][k4 >> 1];
                    uint32_t a0 = (k4 & 1) ? lo.z : lo.x;
                    uint32_t a2 = (k4 & 1) ? lo.w : lo.y;
                    uint32_t a1 = (k4 & 1) ? hi.z : hi.x;
                    uint32_t a3 = (k4 & 1) ? hi.w : hi.y;
                    mma_f16(Co[s], a0, a1, a2, a3, of.x, of.y);
                    mma_f16(Co[s], a0, a1, a2, a3, of.z, of.w);
                }
            }
        }
    }

    // ---- epilogue: bias + tanh.f16x2 + packed store + stats ----
    uint4* toutp = (uint4*)(g_t + (size_t)mslot * BATCH * HID);
    float ssum[16], ssq[16];
    #pragma unroll
    for (int i = 0; i < 16; i++) { ssum[i] = 0.f; ssq[i] = 0.f; }

    #pragma unroll
    for (int s = 0; s < 2; s++) {
        uint32_t w0[8], w1[8];
        #pragma unroll
        for (int n8 = 0; n8 < 8; n8++) {
            int col = n8 * 8 + tig * 2;
            float b0 = g_cbias[col], b1 = g_cbias[col + 1];
            uint32_t h0 = tanh_h2(packf2h2(C[s][n8][0] + b0, C[s][n8][1] + b1));
            uint32_t h1 = tanh_h2(packf2h2(C[s][n8][2] + b0, C[s][n8][3] + b1));
            w0[n8] = h0; w1[n8] = h1;
            float2 f0 = h2f2(h0), f1 = h2f2(h1);
            ssum[2*n8]   += f0.x + f1.x;  ssq[2*n8]   += f0.x*f0.x + f1.x*f1.x;
            ssum[2*n8+1] += f0.y + f1.y;  ssq[2*n8+1] += f0.y*f0.y + f1.y*f1.y;
        }
        size_t r = rb[s];
        toutp[r * 8 + tig * 2]           = make_uint4(w0[0], w0[1], w0[2], w0[3]);
        toutp[r * 8 + tig * 2 + 1]       = make_uint4(w0[4], w0[5], w0[6], w0[7]);
        toutp[(r + 8) * 8 + tig * 2]     = make_uint4(w1[0], w1[1], w1[2], w1[3]);
        toutp[(r + 8) * 8 + tig * 2 + 1] = make_uint4(w1[4], w1[5], w1[6], w1[7]);
    }

    if (FUSE) {
        #pragma unroll
        for (int s = 0; s < 2; s++) {
            size_t r = rb[s];
            int n = 2 * tig;
            if (n < 3) {
                g_pout[r * 3 + n]       = Co[s][0];
                g_pout[(r + 8) * 3 + n] = Co[s][2];
            }
            if (n + 1 < 3) {
                g_pout[r * 3 + n + 1]       = Co[s][1];
                g_pout[(r + 8) * 3 + n + 1] = Co[s][3];
            }
        }
    }

    #pragma unroll
    for (int i = 0; i < 16; i++) {
        ssum[i] += __shfl_xor_sync(0xffffffffu, ssum[i], 4);
        ssq[i]  += __shfl_xor_sync(0xffffffffu, ssq[i], 4);
        ssum[i] += __shfl_xor_sync(0xffffffffu, ssum[i], 8);
        ssq[i]  += __shfl_xor_sync(0xffffffffu, ssq[i], 8);
        ssum[i] += __shfl_xor_sync(0xffffffffu, ssum[i], 16);
        ssq[i]  += __shfl_xor_sync(0xffffffffu, ssq[i], 16);
    }
    __syncthreads();
    if (lane < 4) {
        #pragma unroll
        for (int n8 = 0; n8 < 8; n8++) {
            int col = n8 * 8 + lane * 2;
            atomicAdd(&s_sum[col],     ssum[2 * n8]);
            atomicAdd(&s_sum[col + 1], ssum[2 * n8 + 1]);
            atomicAdd(&s_sq[col],      ssq[2 * n8]);
            atomicAdd(&s_sq[col + 1],  ssq[2 * n8 + 1]);
        }
    }
    __syncthreads();
    if (tid < 64) {
        atomicAdd(&g_sums[mslot + 1][0][tid], s_sum[tid]);
        atomicAdd(&g_sums[mslot + 1][1][tid], s_sq[tid]);
    }
}

// final: out = g_pout + t4 @ (sc4*Wout) + bout2. MMA-based, 128 rows/CTA.
__global__ __launch_bounds__(256) void out2_kernel(float* __restrict__ out) {
    int tid = threadIdx.x, warp = tid >> 5, lane = tid & 31;
    int gid = lane >> 2, tig = lane & 3;
    size_t r = (size_t)blockIdx.x * 128 + warp * 16 + gid;
    int n = 2 * tig;

    float Co[4];
    Co[0] = (n < 3)     ? g_pout[r * 3 + n]           : 0.f;
    Co[1] = (n + 1 < 3) ? g_pout[r * 3 + n + 1]       : 0.f;
    Co[2] = (n < 3)     ? g_pout[(r + 8) * 3 + n]     : 0.f;
    Co[3] = (n + 1 < 3) ? g_pout[(r + 8) * 3 + n + 1] : 0.f;

    const uint4* tp = (const uint4*)(g_t + (size_t)4 * BATCH * HID);
    uint4 A[2][2];
    #pragma unroll
    for (int rh = 0; rh < 2; rh++) {
        size_t base = (r + rh * 8) * 8 + tig * 2;
        A[rh][0] = tp[base];
        A[rh][1] = tp[base + 1];
    }
    #pragma unroll
    for (int k4 = 0; k4 < 4; k4++) {
        uint4 of = g_OBfrag[(4 * 4 + k4) * 32 + lane];
        uint4 lo = A[0][k4 >> 1];
        uint4 hi = A[1][k4 >> 1];
        uint32_t a0 = (k4 & 1) ? lo.z : lo.x;
        uint32_t a2 = (k4 & 1) ? lo.w : lo.y;
        uint32_t a1 = (k4 & 1) ? hi.z : hi.x;
        uint32_t a3 = (k4 & 1) ? hi.w : hi.y;
        mma_f16(Co, a0, a1, a2, a3, of.x, of.y);
        mma_f16(Co, a0, a1, a2, a3, of.z, of.w);
    }

    if (n < 3) {
        float bo = g_bout2[n];
        out[r * 3 + n]       = Co[0] + bo;
        out[(r + 8) * 3 + n] = Co[2] + bo;
    }
    if (n + 1 < 3) {
        float bo = g_bout2[n + 1];
        out[r * 3 + n + 1]       = Co[1] + bo;
        out[(r + 8) * 3 + n + 1] = Co[3] + bo;
    }
}

// ---------------- launch ----------------
extern "C" void kernel_launch(void* const* d_in, const int* in_sizes, int n_in,
                              void* d_out, int out_size) {
    const float* x    = (const float*)d_in[0];
    const float* bn0g = (const float*)d_in[1];
    const float* bn0b = (const float*)d_in[2];
    const float* W0   = (const float*)d_in[3];
    const float* b0   = (const float*)d_in[4];
    const float* g0   = (const float*)d_in[5];
    const float* be0  = (const float*)d_in[6];
    const float* Wh   = (const float*)d_in[7];
    const float* bh   = (const float*)d_in[8];
    const float* gh   = (const float*)d_in[9];
    const float* beh  = (const float*)d_in[10];
    const float* Wo   = (const float*)d_in[11];
    const float* bo   = (const float*)d_in[12];
    float* out = (float*)d_out;

    zero_kernel<<<3, 256>>>();
    xstats_kernel<<<1024, 256>>>(x);
    fin_kernel<<<1, 64>>>(0, bn0g, bn0b, 4);
    k1_kernel<<<8192, 256>>>(x, W0, b0);
    fin_kernel<<<1, 64>>>(1, g0, be0, 64);

    for (int m = 1; m <= 4; m++) {
        prep_kernel<<<m * 4 + 5, 256>>>(m, Wh + (size_t)(m - 1) * 4096, bh + (m - 1) * 64, Wo);
        switch (m) {
            case 1: midk<1, false><<<4096, 256>>>(m); break;
            case 2: midk<2, false><<<4096, 256>>>(m); break;
            case 3: midk<3, false><<<4096, 256>>>(m); break;
            case 4: midk<4, true ><<<4096, 256>>>(m); break;
        }
        fin_kernel<<<1, 64>>>(m + 1, gh + (m - 1) * 64, beh + (m - 1) * 64, 64);
    }
    prepout_kernel<<<5, 64>>>(Wo, bo);
    out2_kernel<<<8192, 256>>>(out);
}